// round 6
// baseline (speedup 1.0000x reference)
#include <cuda_runtime.h>
#include <math.h>

#define BB 32
#define DIN 1024
#define DOUT 1024
#define BETA 0.9f
#define LEAK 0.9f

#define KTILE 16
#define NSPLIT (DIN / KTILE)   /* 64 */
#define BSPLIT 4
#define BQ (BB / BSPLIT)       /* 8 */
#define JSPAN 512              /* 128 threads * 4 j each */
#define NJT (DOUT / JSPAN)     /* 2 */

/* output offsets (floats), in reference return order:
   s, E_W2, E_b2, Rh_W2, Rh_b2, g_bar2, r2 */
#define OFF_S  0
#define OFF_EW (BB * DOUT)
#define OFF_EB (OFF_EW + BB * DIN * DOUT)
#define OFF_RW (OFF_EB + BB * DOUT)
#define OFF_RB (OFF_RW + BB * DIN * DOUT)
#define OFF_G  (OFF_RB + BB * DOUT)
#define OFF_R  (OFF_G + BB * DOUT)

__device__ float g_hpart[NSPLIT][BB * DOUT];     /* 8 MB scratch, fully rewritten every call */

/* ---------------- kernel 1: split-K GEMM, h partials ------------------- */
/* grid (2, 64, 4) = 512 blocks, 128 threads. Each thread owns 4 consecutive
   j columns (float4 W loads -> LDG.128) and 8 batch accumulators.
   Per thread: 16 LDG.128 of W, 512 FMA. */
__global__ void __launch_bounds__(128) gemm_partial(const float* __restrict__ x,
                                                    const float* __restrict__ W) {
    __shared__ float xs[BQ][KTILE];              /* 512 B */
    const int jt  = blockIdx.x;
    const int ks  = blockIdx.y;
    const int bs  = blockIdx.z;
    const int tid = threadIdx.x;
    const int j   = jt * JSPAN + tid * 4;
    const int k0  = ks * KTILE;
    const int b0  = bs * BQ;

    if (tid < BQ * KTILE) {                      /* 128 elements, 1 per thread */
        int bb = tid >> 4, kk = tid & 15;
        xs[bb][kk] = x[(b0 + bb) * DIN + k0 + kk];
    }
    __syncthreads();

    float4 acc[BQ];
#pragma unroll
    for (int bb = 0; bb < BQ; bb++) acc[bb] = make_float4(0.f, 0.f, 0.f, 0.f);

#pragma unroll
    for (int kk = 0; kk < KTILE; kk++) {
        const float4 w = *(const float4*)&W[(k0 + kk) * DOUT + j];
#pragma unroll
        for (int bb = 0; bb < BQ; bb++) {
            const float xv = xs[bb][kk];
            acc[bb].x = fmaf(xv, w.x, acc[bb].x);
            acc[bb].y = fmaf(xv, w.y, acc[bb].y);
            acc[bb].z = fmaf(xv, w.z, acc[bb].z);
            acc[bb].w = fmaf(xv, w.w, acc[bb].w);
        }
    }

#pragma unroll
    for (int bb = 0; bb < BQ; bb++)
        *(float4*)&g_hpart[ks][(b0 + bb) * DOUT + j] = acc[bb];
}

/* ---------------- kernel 2: activation + all small outputs ------------- */
/* float4 over j: 8192 threads, each produces 4 outputs. */
__global__ void __launch_bounds__(256) act_small(const float4* __restrict__ bias4,
                                                 const float4* __restrict__ u4,
                                                 const float4* __restrict__ E_b4,
                                                 const float4* __restrict__ Rh_b4,
                                                 const float4* __restrict__ g_bar4,
                                                 const float* __restrict__ r,
                                                 float* __restrict__ out) {
    const int idx4 = blockIdx.x * 256 + threadIdx.x;   /* 0..8191 */
    const int bb = idx4 >> 8;                           /* / (DOUT/4) */
    const int j4 = idx4 & 255;

    float4 h = bias4[j4];
#pragma unroll
    for (int ks = 0; ks < NSPLIT; ks++) {
        const float4 p = ((const float4*)g_hpart[ks])[idx4];
        h.x += p.x; h.y += p.y; h.z += p.z; h.w += p.w;
    }

    const float4 uu = u4[idx4];
    const float4 eb = E_b4[idx4];
    const float4 rb = Rh_b4[idx4];
    const float4 gb = g_bar4[idx4];

    const float ratio0 = LEAK * r[bb];
    const float r2 = ratio0 + 1.0f;
    const float ratio = ratio0 / r2;

    float4 so, ebo, rbo, go;

    {
        const float un = BETA * uu.x + h.x;
        const float s  = 1.0f / (1.0f + expf(-(un - 1.0f)));
        const float sg = s * (1.0f - s);
        const float a  = BETA * sg;
        so.x = s;
        const float eb1 = BETA * eb.x + 1.0f;
        ebo.x = BETA * eb1 + 1.0f;
        rbo.x = a * rb.x + (a * eb1 + sg);
        go.x  = ratio * gb.x + (1.0f - ratio) * a;
    }
    {
        const float un = BETA * uu.y + h.y;
        const float s  = 1.0f / (1.0f + expf(-(un - 1.0f)));
        const float sg = s * (1.0f - s);
        const float a  = BETA * sg;
        so.y = s;
        const float eb1 = BETA * eb.y + 1.0f;
        ebo.y = BETA * eb1 + 1.0f;
        rbo.y = a * rb.y + (a * eb1 + sg);
        go.y  = ratio * gb.y + (1.0f - ratio) * a;
    }
    {
        const float un = BETA * uu.z + h.z;
        const float s  = 1.0f / (1.0f + expf(-(un - 1.0f)));
        const float sg = s * (1.0f - s);
        const float a  = BETA * sg;
        so.z = s;
        const float eb1 = BETA * eb.z + 1.0f;
        ebo.z = BETA * eb1 + 1.0f;
        rbo.z = a * rb.z + (a * eb1 + sg);
        go.z  = ratio * gb.z + (1.0f - ratio) * a;
    }
    {
        const float un = BETA * uu.w + h.w;
        const float s  = 1.0f / (1.0f + expf(-(un - 1.0f)));
        const float sg = s * (1.0f - s);
        const float a  = BETA * sg;
        so.w = s;
        const float eb1 = BETA * eb.w + 1.0f;
        ebo.w = BETA * eb1 + 1.0f;
        rbo.w = a * rb.w + (a * eb1 + sg);
        go.w  = ratio * gb.w + (1.0f - ratio) * a;
    }

    ((float4*)(out + OFF_S))[idx4]  = so;
    ((float4*)(out + OFF_EB))[idx4] = ebo;
    ((float4*)(out + OFF_RB))[idx4] = rbo;
    ((float4*)(out + OFF_G))[idx4]  = go;
    if (j4 == 0) out[OFF_R + bb] = r2;
}

/* ---------------- kernel 3: big streaming trace update ----------------- */
/* One float4 per thread: 32 B in (E_W, Rh_W), 32 B out (E_W2, Rh_W2).
   Streaming cache hints keep the 512 MB from churning L2 so the s / x
   reads stay L2-resident. */
__global__ void __launch_bounds__(256) big_update(const float* __restrict__ x,
                                                  const float4* __restrict__ E_W,
                                                  const float4* __restrict__ Rh_W,
                                                  float* __restrict__ out) {
    const float4* __restrict__ s4p = (const float4*)(out + OFF_S);
    float4* __restrict__ ew2 = (float4*)(out + OFF_EW);
    float4* __restrict__ rw2 = (float4*)(out + OFF_RW);

    const int idx = blockIdx.x * 256 + threadIdx.x;   /* 0..8388607 */
    const int bb  = idx >> 18;
    const int rem = idx & 262143;
    const int i   = rem >> 8;
    const int j4  = rem & 255;

    /* DRAM streams first for max MLP, evict-first policy */
    const float4 ew = __ldcs(&E_W[idx]);
    const float4 rh = __ldcs(&Rh_W[idx]);
    const float  xv = __ldg(&x[bb * DIN + i]);
    const float4 s4 = s4p[bb * 256 + j4];

    float4 o1, o2;

    {
        const float sg = s4.x * (1.0f - s4.x);
        const float a  = BETA * sg;
        const float e1 = fmaf(BETA, ew.x, xv);
        o1.x = fmaf(BETA, e1, xv);
        o2.x = fmaf(a, rh.x, fmaf(a, e1, xv * sg));
    }
    {
        const float sg = s4.y * (1.0f - s4.y);
        const float a  = BETA * sg;
        const float e1 = fmaf(BETA, ew.y, xv);
        o1.y = fmaf(BETA, e1, xv);
        o2.y = fmaf(a, rh.y, fmaf(a, e1, xv * sg));
    }
    {
        const float sg = s4.z * (1.0f - s4.z);
        const float a  = BETA * sg;
        const float e1 = fmaf(BETA, ew.z, xv);
        o1.z = fmaf(BETA, e1, xv);
        o2.z = fmaf(a, rh.z, fmaf(a, e1, xv * sg));
    }
    {
        const float sg = s4.w * (1.0f - s4.w);
        const float a  = BETA * sg;
        const float e1 = fmaf(BETA, ew.w, xv);
        o1.w = fmaf(BETA, e1, xv);
        o2.w = fmaf(a, rh.w, fmaf(a, e1, xv * sg));
    }

    __stcs(&ew2[idx], o1);
    __stcs(&rw2[idx], o2);
}

extern "C" void kernel_launch(void* const* d_in, const int* in_sizes, int n_in,
                              void* d_out, int out_size) {
    const float* x     = (const float*)d_in[0];
    const float* W     = (const float*)d_in[1];
    const float* bias  = (const float*)d_in[2];
    const float* u     = (const float*)d_in[3];
    const float* E_b   = (const float*)d_in[5];
    const float* Rh_b  = (const float*)d_in[7];
    const float* g_bar = (const float*)d_in[8];
    const float* r     = (const float*)d_in[9];
    const float* E_W   = (const float*)d_in[4];
    const float* Rh_W  = (const float*)d_in[6];
    float* out = (float*)d_out;

    dim3 gg(NJT, NSPLIT, BSPLIT);
    gemm_partial<<<gg, 128>>>(x, W);
    act_small<<<BB * DOUT / 4 / 256, 256>>>((const float4*)bias, (const float4*)u,
                                            (const float4*)E_b, (const float4*)Rh_b,
                                            (const float4*)g_bar, r, out);
    big_update<<<(BB * DIN * DOUT / 4) / 256, 256>>>(x, (const float4*)E_W,
                                                     (const float4*)Rh_W, out);
}